// round 10
// baseline (speedup 1.0000x reference)
#include <cuda_runtime.h>
#include <cstdint>

#define BATCH 4
#define LSEQ 4096
#define DMODEL_ 1024
#define DKH 64
#define MROWS (BATCH*LSEQ)   // 16384
#define NQB (LSEQ/64)        // 64 q-blocks per batch
#define KCHUNK 8             // key tiles per split-K work item
#define MAXCH (NQB/KCHUNK)   // 8 chunks max per q-block
#define NTILES (BATCH*NQB)   // 256 key tiles total

// projected q,k,v as fp16 (half2 packed in uint32), row-major [row][32 half2]
// q pre-scaled by 0.125
__device__ uint32_t g_q[MROWS*32];
__device__ uint32_t g_k[MROWS*32];
__device__ uint32_t g_v[MROWS*32];

// fp16 B-fragment-ordered weights: [slice 3][kt 64][ntp 4][lane 32] uint4
__device__ uint4 g_wf16[3*8192];

// mma-fragment-ordered K/V tiles (fp16): per tile 512 uint4 (8KB)
__device__ uint4 g_kf[NTILES*512];
__device__ uint4 g_vf[NTILES*512];

// split-K partials: item = (b*64+qb)*8 + ci
__device__ float g_opart[(size_t)BATCH*NQB*MAXCH*4096];
__device__ float g_lpart[BATCH*NQB*MAXCH*64];

// pack two fp32 -> half2 (lo in low half)
__device__ __forceinline__ uint32_t packh2(float lo, float hi) {
    uint32_t d;
    asm("cvt.rn.f16x2.f32 %0, %1, %2;" : "=r"(d) : "f"(hi), "f"(lo));
    return d;
}

__device__ __forceinline__ void mma_f16(float c[4],
    uint32_t a0, uint32_t a1, uint32_t a2, uint32_t a3,
    uint32_t b0, uint32_t b1)
{
    asm volatile(
        "mma.sync.aligned.m16n8k16.row.col.f32.f16.f16.f32 "
        "{%0,%1,%2,%3}, {%4,%5,%6,%7}, {%8,%9}, {%0,%1,%2,%3};\n"
        : "+f"(c[0]), "+f"(c[1]), "+f"(c[2]), "+f"(c[3])
        : "r"(a0), "r"(a1), "r"(a2), "r"(a3), "r"(b0), "r"(b1));
}

__device__ __forceinline__ void cp16(uint32_t saddr, const void* g) {
    asm volatile("cp.async.cg.shared.global [%0], [%1], 16;" :: "r"(saddr), "l"(g));
}
#define CP_COMMIT() asm volatile("cp.async.commit_group;")
#define CP_WAIT0()  asm volatile("cp.async.wait_group 0;")

// ---------------------------------------------------------------------------
// Setup: fp16 fragment-ordered W. idx -> (slice, kt 0..63, ntp 0..3, lane).
// ---------------------------------------------------------------------------
__global__ void wfrag16_kernel(const float* __restrict__ Wq,
                               const float* __restrict__ Wk,
                               const float* __restrict__ Wv)
{
    int idx = blockIdx.x * 256 + threadIdx.x;   // 24576 total
    int slice = idx >> 13;
    int rem = idx & 8191;
    int kt = rem >> 7;
    int ntp = (rem >> 5) & 3;
    int l = rem & 31;
    int g = l >> 2, t = l & 3;
    const float* W = (slice == 0) ? Wq : (slice == 1) ? Wk : Wv;
    int n0 = 2 * ntp * 8 + g;
    int k0 = 16 * kt + 2 * t;
    uint4 v;
    v.x = packh2(W[k0 * DKH + n0],           W[(k0 + 1) * DKH + n0]);
    v.y = packh2(W[(k0 + 8) * DKH + n0],     W[(k0 + 9) * DKH + n0]);
    v.z = packh2(W[k0 * DKH + n0 + 8],       W[(k0 + 1) * DKH + n0 + 8]);
    v.w = packh2(W[(k0 + 8) * DKH + n0 + 8], W[(k0 + 9) * DKH + n0 + 8]);
    g_wf16[idx] = v;
}

// ---------------------------------------------------------------------------
// Projection v5 (fp16 m16n8k16): Y[16384,64] = fp16( X @ W + bias )
// CTA = 64 rows, 512 threads (16 warps = 4 row-groups x 4 col-groups).
// X read as long sequential bursts (LDG.128 -> cvt f16x2 -> STS.64), chunked
// by k=256, fp16 staged in a 2-deep ring (33 KB/stage). Full fragment-ordered
// W (128 KB) resident in smem per CTA, staged once via cp.async.
// A-frags: 4 conflict-free LDS.32; B-frags: 1 LDS.128 -> 2 mma.
// grid = (256, 1, 3); z selects {q,k,v}
// ---------------------------------------------------------------------------
#define P5_XSTRIDE 132                        // u32 words per row (+4 pad)
#define P5_XSTAGE_W (64*P5_XSTRIDE)           // 8448 u32 = 33792 B
#define P5_WOFF (2*P5_XSTAGE_W)               // u32 offset of W frags
#define P5_SMEM_BYTES (2*P5_XSTAGE_W*4 + 131072)   // 198656

__global__ __launch_bounds__(512, 1) void proj5_kernel(
    const float* __restrict__ Qin, const float* __restrict__ Kin, const float* __restrict__ Vin,
    const float* __restrict__ bq, const float* __restrict__ bk, const float* __restrict__ bv)
{
    extern __shared__ uint32_t sm[];
    uint32_t* Xs = sm;                         // [2][64*132] u32 (fp16 pairs)
    const uint4* Wf = (const uint4*)(sm + P5_WOFF);   // [64 kt][4 ntp][32] uint4
    const uint32_t wsb = (uint32_t)__cvta_generic_to_shared(sm + P5_WOFF);

    const int which = blockIdx.z;
    const float* X    = (which == 0) ? Qin : (which == 1) ? Kin : Vin;
    const float* bias = (which == 0) ? bq  : (which == 1) ? bk  : bv;
    uint32_t* Y       = (which == 0) ? g_q : (which == 1) ? g_k : g_v;
    const float scale = (which == 0) ? 0.125f : 1.0f;

    const int tid = threadIdx.x;
    const int w = tid >> 5;
    const int l = tid & 31;
    const int g = l >> 2;
    const int t = l & 3;
    const int rg = w & 3;      // row group: rows 16rg..16rg+15
    const int cg = w >> 2;     // col group: cols 16cg..16cg+15 (ntp = cg)
    const int row_base = blockIdx.x * 64;
    const float* Xp = X + (size_t)row_base * DMODEL_;
    const uint4* wsrc = g_wf16 + which * 8192;

    // per-thread X mapping: f = tid + j*512 -> row f>>6, float4-col f&63
    const int xrow = tid >> 6;                 // base rows handled: xrow, xrow+8,.. (j adds 8 rows per step of 512? no: f>>6 increments by 8 per j)
    const int xc4 = tid & 63;

    float acc[2][4];
    #pragma unroll
    for (int p = 0; p < 2; p++)
        #pragma unroll
        for (int j = 0; j < 4; j++) acc[p][j] = 0.f;

    float4 xr[8];

    // LDG one chunk (64 rows x 256 cols fp32) into registers
    auto ldchunk = [&](int ch) {
        #pragma unroll
        for (int j = 0; j < 8; j++) {
            int row = xrow + j * 8;
            xr[j] = *(const float4*)&Xp[(size_t)row * DMODEL_ + ch * 256 + xc4 * 4];
        }
    };
    // cvt + STS chunk into stage buffer s
    auto stchunk = [&](int s) {
        uint32_t* Xb = Xs + s * P5_XSTAGE_W;
        #pragma unroll
        for (int j = 0; j < 8; j++) {
            int row = xrow + j * 8;
            int word = row * P5_XSTRIDE + 2 * xc4;
            Xb[word]     = packh2(xr[j].x, xr[j].y);
            Xb[word + 1] = packh2(xr[j].z, xr[j].w);
        }
    };

    // prologue: stage W (cp.async), chunk 0 via LDG
    #pragma unroll
    for (int i = 0; i < 16; i++) {
        int u = tid + i * 512;
        cp16(wsb + (uint32_t)u * 16, wsrc + u);
    }
    CP_COMMIT();
    ldchunk(0);
    stchunk(0);
    CP_WAIT0();
    __syncthreads();
    ldchunk(1);

    const int abase = (16 * rg + g) * P5_XSTRIDE + t;

    for (int ch = 0; ch < 4; ch++) {
        const uint32_t* Xc = Xs + (ch & 1) * P5_XSTAGE_W;

        #pragma unroll
        for (int kk = 0; kk < 16; kk++) {
            int aw = abase + kk * 8;
            uint32_t a0 = Xc[aw];
            uint32_t a1 = Xc[aw + 8 * P5_XSTRIDE];
            uint32_t a2 = Xc[aw + 4];
            uint32_t a3 = Xc[aw + 8 * P5_XSTRIDE + 4];
            uint4 f = Wf[((ch * 16 + kk) * 4 + cg) * 32 + l];
            mma_f16(acc[0], a0, a1, a2, a3, f.x, f.y);
            mma_f16(acc[1], a0, a1, a2, a3, f.z, f.w);
        }

        if (ch < 3) stchunk((ch + 1) & 1);
        __syncthreads();
        if (ch < 2) ldchunk(ch + 2);
    }

    // epilogue: +bias, *scale, pack fp16; warp covers cols 16cg..16cg+15
    #pragma unroll
    for (int p = 0; p < 2; p++) {
        int nt = 2 * cg + p;
        int c = nt * 8 + 2 * t;
        float b0v = bias[c], b1v = bias[c + 1];
        int r = row_base + 16 * rg + g;
        Y[(size_t)r * 32 + nt * 4 + t] =
            packh2((acc[p][0] + b0v) * scale, (acc[p][1] + b1v) * scale);
        Y[(size_t)(r + 8) * 32 + nt * 4 + t] =
            packh2((acc[p][2] + b0v) * scale, (acc[p][3] + b1v) * scale);
    }
}

// ---------------------------------------------------------------------------
// Repack K/V into mma B-fragment order (fp16). (unchanged)
// ---------------------------------------------------------------------------
__global__ void repack_kernel()
{
    int idx = blockIdx.x * 256 + threadIdx.x;   // 131072
    int T = idx >> 9;
    int r = idx & 511;
    int kt = r >> 7;
    int ntp = (r >> 5) & 3;
    int l = r & 31;
    int g = l >> 2, t = l & 3;
    int row0 = T * 64;

    const uint32_t* ku = g_k;
    const unsigned short* vh = (const unsigned short*)g_v;

    uint4 kv, vv;
    {
        int nt = 2 * ntp;
        int key = row0 + nt * 8 + g;
        kv.x = ku[(size_t)key * 32 + kt * 8 + t];
        kv.y = ku[(size_t)key * 32 + kt * 8 + t + 4];
        key += 8;
        kv.z = ku[(size_t)key * 32 + kt * 8 + t];
        kv.w = ku[(size_t)key * 32 + kt * 8 + t + 4];
    }
    {
        int kr = row0 + kt * 16;
        int nt = 2 * ntp;
        int col = nt * 8 + g;
        unsigned v0 = vh[(size_t)(kr + 2 * t) * 64 + col];
        unsigned v1 = vh[(size_t)(kr + 2 * t + 1) * 64 + col];
        unsigned v2 = vh[(size_t)(kr + 2 * t + 8) * 64 + col];
        unsigned v3 = vh[(size_t)(kr + 2 * t + 9) * 64 + col];
        vv.x = v0 | (v1 << 16);
        vv.y = v2 | (v3 << 16);
        col += 8;
        v0 = vh[(size_t)(kr + 2 * t) * 64 + col];
        v1 = vh[(size_t)(kr + 2 * t + 1) * 64 + col];
        v2 = vh[(size_t)(kr + 2 * t + 8) * 64 + col];
        v3 = vh[(size_t)(kr + 2 * t + 9) * 64 + col];
        vv.z = v0 | (v1 << 16);
        vv.w = v2 | (v3 << 16);
    }
    g_kf[idx] = kv;
    g_vf[idx] = vv;
}

// ---------------------------------------------------------------------------
// Attention stage 1 (fp16 m16n8k16): split-K partials. (unchanged)
// grid = (8 ci, 64 qb, 4 b)
// ---------------------------------------------------------------------------
#define ATT_SMEM_BYTES 32768

__global__ __launch_bounds__(256, 2) void attn_part_kernel()
{
    extern __shared__ uint4 sm4[];
    const uint32_t smb = (uint32_t)__cvta_generic_to_shared(sm4);

    const int ci = blockIdx.x;
    const int qb = blockIdx.y;
    const int b  = blockIdx.z;
    const int kstart = ci * KCHUNK;
    if (kstart > qb) return;
    const int kend = min(kstart + KCHUNK, qb + 1);

    const int tid = threadIdx.x;
    const int w = tid >> 5;
    const int l = tid & 31;
    const int g = l >> 2;
    const int t = l & 3;
    const int wr = w & 3;
    const int wg = w >> 2;

    uint32_t qa[4][4];
    {
        const uint32_t* qu = g_q + ((size_t)b * LSEQ + (size_t)qb * 64 + 16 * wr + g) * 32;
        const uint32_t* qu8 = qu + 8 * 32;
        #pragma unroll
        for (int kt = 0; kt < 4; kt++) {
            qa[kt][0] = qu[kt * 8 + t];
            qa[kt][1] = qu8[kt * 8 + t];
            qa[kt][2] = qu[kt * 8 + t + 4];
            qa[kt][3] = qu8[kt * 8 + t + 4];
        }
    }

    float o[8][4];
    #pragma unroll
    for (int nt = 0; nt < 8; nt++)
        #pragma unroll
        for (int j = 0; j < 4; j++) o[nt][j] = 0.f;
    float lsum0 = 0.f, lsum1 = 0.f;

    auto stage = [&](int kb, int p) {
        const uint4* kp = g_kf + (size_t)(b * NQB + kb) * 512;
        const uint4* vp = g_vf + (size_t)(b * NQB + kb) * 512;
        uint32_t kd = smb + (uint32_t)p * 8192;
        uint32_t vd = smb + 16384u + (uint32_t)p * 8192;
        #pragma unroll
        for (int i = 0; i < 2; i++) {
            int u = tid + i * 256;
            cp16(kd + (uint32_t)u * 16, kp + u);
            cp16(vd + (uint32_t)u * 16, vp + u);
        }
        CP_COMMIT();
    };

    stage(kstart, 0);

    for (int kb = kstart; kb < kend; kb++) {
        const int p = (kb - kstart) & 1;
        CP_WAIT0();
        __syncthreads();
        const uint4* Kc = sm4 + p * 512;
        const uint4* Vc = sm4 + 1024 + p * 512;

        if (kb + 1 < kend) stage(kb + 1, 1 - p);

        float s[4][4];
        #pragma unroll
        for (int ntl = 0; ntl < 4; ntl++)
            #pragma unroll
            for (int j = 0; j < 4; j++) s[ntl][j] = 0.f;

        #pragma unroll
        for (int kt = 0; kt < 4; kt++) {
            #pragma unroll
            for (int pp = 0; pp < 2; pp++) {
                uint4 f = Kc[(kt * 4 + wg * 2 + pp) * 32 + l];
                mma_f16(s[2 * pp],     qa[kt][0], qa[kt][1], qa[kt][2], qa[kt][3], f.x, f.y);
                mma_f16(s[2 * pp + 1], qa[kt][0], qa[kt][1], qa[kt][2], qa[kt][3], f.z, f.w);
            }
        }

        if (kb == qb) {
            int r0 = 16 * wr + g;
            #pragma unroll
            for (int ntl = 0; ntl < 4; ntl++) {
                int c = (wg * 4 + ntl) * 8 + 2 * t;
                if (c     > r0)     s[ntl][0] = -1e30f;
                if (c + 1 > r0)     s[ntl][1] = -1e30f;
                if (c     > r0 + 8) s[ntl][2] = -1e30f;
                if (c + 1 > r0 + 8) s[ntl][3] = -1e30f;
            }
        }

        #pragma unroll
        for (int ntl = 0; ntl < 4; ntl++) {
            s[ntl][0] = __expf(s[ntl][0]);
            s[ntl][1] = __expf(s[ntl][1]);
            s[ntl][2] = __expf(s[ntl][2]);
            s[ntl][3] = __expf(s[ntl][3]);
            lsum0 += s[ntl][0] + s[ntl][1];
            lsum1 += s[ntl][2] + s[ntl][3];
        }

        #pragma unroll
        for (int kk = 0; kk < 2; kk++) {
            uint32_t a0 = packh2(s[2 * kk][0],     s[2 * kk][1]);
            uint32_t a1 = packh2(s[2 * kk][2],     s[2 * kk][3]);
            uint32_t a2 = packh2(s[2 * kk + 1][0], s[2 * kk + 1][1]);
            uint32_t a3 = packh2(s[2 * kk + 1][2], s[2 * kk + 1][3]);
            int kc = wg * 2 + kk;
            #pragma unroll
            for (int ntp = 0; ntp < 4; ntp++) {
                uint4 f = Vc[(kc * 4 + ntp) * 32 + l];
                mma_f16(o[2 * ntp],     a0, a1, a2, a3, f.x, f.y);
                mma_f16(o[2 * ntp + 1], a0, a1, a2, a3, f.z, f.w);
            }
        }
    }

    lsum0 += __shfl_xor_sync(0xffffffffu, lsum0, 1);
    lsum0 += __shfl_xor_sync(0xffffffffu, lsum0, 2);
    lsum1 += __shfl_xor_sync(0xffffffffu, lsum1, 1);
    lsum1 += __shfl_xor_sync(0xffffffffu, lsum1, 2);

    float* smemO = (float*)sm4;
    float* lvec  = (float*)sm4 + 64 * 68;

    __syncthreads();
    if (wg == 0) {
        #pragma unroll
        for (int nt = 0; nt < 8; nt++) {
            int c = nt * 8 + 2 * t;
            smemO[(16 * wr + g) * 68 + c]         = o[nt][0];
            smemO[(16 * wr + g) * 68 + c + 1]     = o[nt][1];
            smemO[(16 * wr + g + 8) * 68 + c]     = o[nt][2];
            smemO[(16 * wr + g + 8) * 68 + c + 1] = o[nt][3];
        }
        if (t == 0) { lvec[16 * wr + g] = lsum0; lvec[16 * wr + g + 8] = lsum1; }
    }
    __syncthreads();
    if (wg == 1) {
        #pragma unroll
        for (int nt = 0; nt < 8; nt++) {
            int c = nt * 8 + 2 * t;
            smemO[(16 * wr + g) * 68 + c]         += o[nt][0];
            smemO[(16 * wr + g) * 68 + c + 1]     += o[nt][1];
            smemO[(16 * wr + g + 8) * 68 + c]     += o[nt][2];
            smemO[(16 * wr + g + 8) * 68 + c + 1] += o[nt][3];
        }
        if (t == 0) { lvec[16 * wr + g] += lsum0; lvec[16 * wr + g + 8] += lsum1; }
    }
    __syncthreads();

    const int item = (b * NQB + qb) * MAXCH + ci;
    {
        int row = tid >> 2;
        int c0 = (tid & 3) * 16;
        float* dst = g_opart + (size_t)item * 4096;
        #pragma unroll
        for (int j = 0; j < 4; j++)
            *(float4*)&dst[row * 64 + c0 + j * 4] = *(float4*)&smemO[row * 68 + c0 + j * 4];
        if ((tid & 3) == 0) g_lpart[item * 64 + row] = lvec[row];
    }
}

// ---------------------------------------------------------------------------
// Attention stage 2: elementwise reduce. (unchanged)
// ---------------------------------------------------------------------------
__global__ __launch_bounds__(256) void attn_reduce_kernel(float* __restrict__ out)
{
    int id = blockIdx.x * 256 + threadIdx.x;   // 262144
    int c4  = id & 15;
    int row = (id >> 4) & 63;
    int qb  = (id >> 10) & 63;
    int b   = id >> 16;
    int nch = qb / KCHUNK + 1;
    int base_item = (b * NQB + qb) * MAXCH;

    float4 acc = make_float4(0.f, 0.f, 0.f, 0.f);
    float lac = 0.f;
    for (int ci = 0; ci < nch; ci++) {
        const float4 v = *(const float4*)&g_opart[(size_t)(base_item + ci) * 4096 + row * 64 + c4 * 4];
        acc.x += v.x; acc.y += v.y; acc.z += v.z; acc.w += v.w;
        lac += g_lpart[(base_item + ci) * 64 + row];
    }
    float inv = 1.0f / lac;
    acc.x *= inv; acc.y *= inv; acc.z *= inv; acc.w *= inv;
    size_t orow = ((size_t)b * LSEQ + (size_t)qb * 64 + row) * DKH;
    *(float4*)&out[orow + c4 * 4] = acc;
}

// ---------------------------------------------------------------------------
extern "C" void kernel_launch(void* const* d_in, const int* in_sizes, int n_in,
                              void* d_out, int out_size)
{
    const float* Q  = (const float*)d_in[0];
    const float* K  = (const float*)d_in[1];
    const float* V  = (const float*)d_in[2];
    const float* Wq = (const float*)d_in[3];
    const float* bq = (const float*)d_in[4];
    const float* Wk = (const float*)d_in[5];
    const float* bk = (const float*)d_in[6];
    const float* Wv = (const float*)d_in[7];
    const float* bv = (const float*)d_in[8];
    float* out = (float*)d_out;

    cudaFuncSetAttribute(proj5_kernel, cudaFuncAttributeMaxDynamicSharedMemorySize,
                         P5_SMEM_BYTES);
    cudaFuncSetAttribute(attn_part_kernel, cudaFuncAttributeMaxDynamicSharedMemorySize,
                         ATT_SMEM_BYTES);

    wfrag16_kernel<<<96, 256>>>(Wq, Wk, Wv);

    dim3 pg(MROWS / 64, 1, 3);
    proj5_kernel<<<pg, 512, P5_SMEM_BYTES>>>(Q, K, V, bq, bk, bv);

    repack_kernel<<<512, 256>>>();

    dim3 ag(MAXCH, NQB, BATCH);
    attn_part_kernel<<<ag, 256, ATT_SMEM_BYTES>>>();

    attn_reduce_kernel<<<1024, 256>>>(out);
}

// round 11
// speedup vs baseline: 1.0827x; 1.0827x over previous
#include <cuda_runtime.h>
#include <cstdint>

#define BATCH 4
#define LSEQ 4096
#define DMODEL_ 1024
#define DKH 64
#define MROWS (BATCH*LSEQ)   // 16384
#define NQB (LSEQ/64)        // 64 q-blocks per batch
#define KCHUNK 8             // key tiles per split-K work item
#define MAXCH (NQB/KCHUNK)   // 8 chunks max per q-block
#define NTILES (BATCH*NQB)   // 256 key tiles total

// projected q,k,v as fp16 (half2 packed in uint32), row-major [row][32 half2]
// q pre-scaled by 0.125*log2(e)  (scores come out in log2 domain)
__device__ uint32_t g_q[MROWS*32];
__device__ uint32_t g_k[MROWS*32];
__device__ uint32_t g_v[MROWS*32];

// fp16 B-fragment-ordered weights: [slice 3][kt 64][ntp 4][lane 32] uint4
__device__ uint4 g_wf16[3*8192];

// mma-fragment-ordered K/V tiles (fp16): per tile 512 uint4 (8KB)
__device__ uint4 g_kf[NTILES*512];
__device__ uint4 g_vf[NTILES*512];

// split-K partials: item = (b*64+qb)*8 + ci
__device__ float g_opart[(size_t)BATCH*NQB*MAXCH*4096];
__device__ float g_lpart[BATCH*NQB*MAXCH*64];

// pack two fp32 -> half2 (lo in low half)
__device__ __forceinline__ uint32_t packh2(float lo, float hi) {
    uint32_t d;
    asm("cvt.rn.f16x2.f32 %0, %1, %2;" : "=r"(d) : "f"(hi), "f"(lo));
    return d;
}

__device__ __forceinline__ float ex2f(float x) {
    float r;
    asm("ex2.approx.f32 %0, %1;" : "=f"(r) : "f"(x));
    return r;
}

__device__ __forceinline__ void mma_f16(float c[4],
    uint32_t a0, uint32_t a1, uint32_t a2, uint32_t a3,
    uint32_t b0, uint32_t b1)
{
    asm volatile(
        "mma.sync.aligned.m16n8k16.row.col.f32.f16.f16.f32 "
        "{%0,%1,%2,%3}, {%4,%5,%6,%7}, {%8,%9}, {%0,%1,%2,%3};\n"
        : "+f"(c[0]), "+f"(c[1]), "+f"(c[2]), "+f"(c[3])
        : "r"(a0), "r"(a1), "r"(a2), "r"(a3), "r"(b0), "r"(b1));
}

__device__ __forceinline__ void cp16(uint32_t saddr, const void* g) {
    asm volatile("cp.async.cg.shared.global [%0], [%1], 16;" :: "r"(saddr), "l"(g));
}
#define CP_COMMIT() asm volatile("cp.async.commit_group;")
#define CP_WAIT0()  asm volatile("cp.async.wait_group 0;")
#define CP_WAIT2()  asm volatile("cp.async.wait_group 2;")

// ---------------------------------------------------------------------------
// Setup: fp16 fragment-ordered W. idx -> (slice, kt 0..63, ntp 0..3, lane).
// ---------------------------------------------------------------------------
__global__ void wfrag16_kernel(const float* __restrict__ Wq,
                               const float* __restrict__ Wk,
                               const float* __restrict__ Wv)
{
    int idx = blockIdx.x * 256 + threadIdx.x;   // 24576 total
    int slice = idx >> 13;
    int rem = idx & 8191;
    int kt = rem >> 7;
    int ntp = (rem >> 5) & 3;
    int l = rem & 31;
    int g = l >> 2, t = l & 3;
    const float* W = (slice == 0) ? Wq : (slice == 1) ? Wk : Wv;
    int n0 = 2 * ntp * 8 + g;
    int k0 = 16 * kt + 2 * t;
    uint4 v;
    v.x = packh2(W[k0 * DKH + n0],           W[(k0 + 1) * DKH + n0]);
    v.y = packh2(W[(k0 + 8) * DKH + n0],     W[(k0 + 9) * DKH + n0]);
    v.z = packh2(W[k0 * DKH + n0 + 8],       W[(k0 + 1) * DKH + n0 + 8]);
    v.w = packh2(W[(k0 + 8) * DKH + n0 + 8], W[(k0 + 9) * DKH + n0 + 8]);
    g_wf16[idx] = v;
}

// ---------------------------------------------------------------------------
// Projection v3 (R8 config, best measured): fp16 m16n8k16.
// 256 threads (8 warps), 128 rows/CTA, k=32 chunks, 4 smem stages,
// 3 chunks in flight. Q epilogue scale now folds log2(e).
// grid = (128, 1, 3); z selects {q,k,v}
// ---------------------------------------------------------------------------
#define P3_XSTRIDE 36                        // floats per row in a stage
#define P3_XSTAGE_B (128*P3_XSTRIDE*4)       // 18432 B
#define P3_WSTAGE_B 4096                     // 256 uint4
#define P3_SMEM_BYTES (4*P3_XSTAGE_B + 4*P3_WSTAGE_B)   // 90112

__global__ __launch_bounds__(256, 2) void proj3_kernel(
    const float* __restrict__ Qin, const float* __restrict__ Kin, const float* __restrict__ Vin,
    const float* __restrict__ bq, const float* __restrict__ bk, const float* __restrict__ bv)
{
    extern __shared__ char smraw[];
    const float* Xs = (const float*)smraw;                       // [4][128*36]
    const uint4* Ws = (const uint4*)(smraw + 4 * P3_XSTAGE_B);   // [4][256]
    const uint32_t xsb = (uint32_t)__cvta_generic_to_shared(smraw);
    const uint32_t wsb = xsb + 4 * P3_XSTAGE_B;

    const int which = blockIdx.z;
    const float* X    = (which == 0) ? Qin : (which == 1) ? Kin : Vin;
    const float* bias = (which == 0) ? bq  : (which == 1) ? bk  : bv;
    uint32_t* Y       = (which == 0) ? g_q : (which == 1) ? g_k : g_v;
    // q pre-scale folds 1/sqrt(dk) AND log2(e): exp(S) == 2^(S')
    const float scale = (which == 0) ? 0.125f * 1.44269504088896340736f : 1.0f;

    const int tid = threadIdx.x;
    const int w = tid >> 5;
    const int l = tid & 31;
    const int g = l >> 2;
    const int t = l & 3;
    const int row_base = blockIdx.x * 128;
    const float* Xp = X + (size_t)row_base * DMODEL_;
    const uint4* wsrc = g_wf16 + which * 8192;

    float acc[8][4];
    #pragma unroll
    for (int nt = 0; nt < 8; nt++)
        #pragma unroll
        for (int j = 0; j < 4; j++) acc[nt][j] = 0.f;

    auto issue = [&](int ch) {
        if (ch < 32) {
            uint32_t xb = xsb + (uint32_t)(ch & 3) * P3_XSTAGE_B;
            #pragma unroll
            for (int i = 0; i < 4; i++) {
                int f = tid + i * 256;             // 1024 float4 total
                int r = f >> 3, c = f & 7;
                cp16(xb + (uint32_t)(r * P3_XSTRIDE + c * 4) * 4,
                     Xp + (size_t)r * DMODEL_ + ch * 32 + c * 4);
            }
            uint32_t wb = wsb + (uint32_t)(ch & 3) * P3_WSTAGE_B;
            cp16(wb + (uint32_t)tid * 16, wsrc + ch * 256 + tid);
        }
        CP_COMMIT();
    };

    issue(0); issue(1); issue(2);

    const int r0 = 16 * w + g;
    for (int ch = 0; ch < 32; ch++) {
        CP_WAIT2();
        __syncthreads();
        issue(ch + 3);

        const float* Xc = Xs + (ch & 3) * (128 * P3_XSTRIDE);
        const uint4* Wc = Ws + (ch & 3) * 256;

        #pragma unroll
        for (int kk = 0; kk < 2; kk++) {
            int cb = kk * 16 + 2 * t;
            float2 q0 = *(const float2*)&Xc[r0 * P3_XSTRIDE + cb];
            float2 q1 = *(const float2*)&Xc[(r0 + 8) * P3_XSTRIDE + cb];
            float2 q2 = *(const float2*)&Xc[r0 * P3_XSTRIDE + cb + 8];
            float2 q3 = *(const float2*)&Xc[(r0 + 8) * P3_XSTRIDE + cb + 8];
            uint32_t a0 = packh2(q0.x, q0.y);
            uint32_t a1 = packh2(q1.x, q1.y);
            uint32_t a2 = packh2(q2.x, q2.y);
            uint32_t a3 = packh2(q3.x, q3.y);
            #pragma unroll
            for (int ntp = 0; ntp < 4; ntp++) {
                uint4 f = Wc[(kk * 4 + ntp) * 32 + l];
                mma_f16(acc[2 * ntp],     a0, a1, a2, a3, f.x, f.y);
                mma_f16(acc[2 * ntp + 1], a0, a1, a2, a3, f.z, f.w);
            }
        }
    }

    // epilogue: +bias, *scale, pack fp16 half2
    #pragma unroll
    for (int nt = 0; nt < 8; nt++) {
        int c = nt * 8 + 2 * t;
        float b0v = bias[c], b1v = bias[c + 1];
        Y[(size_t)(row_base + r0) * 32 + nt * 4 + t] =
            packh2((acc[nt][0] + b0v) * scale, (acc[nt][1] + b1v) * scale);
        Y[(size_t)(row_base + r0 + 8) * 32 + nt * 4 + t] =
            packh2((acc[nt][2] + b0v) * scale, (acc[nt][3] + b1v) * scale);
    }
}

// ---------------------------------------------------------------------------
// Repack K/V into mma B-fragment order (fp16). (unchanged)
// ---------------------------------------------------------------------------
__global__ void repack_kernel()
{
    int idx = blockIdx.x * 256 + threadIdx.x;   // 131072
    int T = idx >> 9;
    int r = idx & 511;
    int kt = r >> 7;
    int ntp = (r >> 5) & 3;
    int l = r & 31;
    int g = l >> 2, t = l & 3;
    int row0 = T * 64;

    const uint32_t* ku = g_k;
    const unsigned short* vh = (const unsigned short*)g_v;

    uint4 kv, vv;
    {
        int nt = 2 * ntp;
        int key = row0 + nt * 8 + g;
        kv.x = ku[(size_t)key * 32 + kt * 8 + t];
        kv.y = ku[(size_t)key * 32 + kt * 8 + t + 4];
        key += 8;
        kv.z = ku[(size_t)key * 32 + kt * 8 + t];
        kv.w = ku[(size_t)key * 32 + kt * 8 + t + 4];
    }
    {
        int kr = row0 + kt * 16;
        int nt = 2 * ntp;
        int col = nt * 8 + g;
        unsigned v0 = vh[(size_t)(kr + 2 * t) * 64 + col];
        unsigned v1 = vh[(size_t)(kr + 2 * t + 1) * 64 + col];
        unsigned v2 = vh[(size_t)(kr + 2 * t + 8) * 64 + col];
        unsigned v3 = vh[(size_t)(kr + 2 * t + 9) * 64 + col];
        vv.x = v0 | (v1 << 16);
        vv.y = v2 | (v3 << 16);
        col += 8;
        v0 = vh[(size_t)(kr + 2 * t) * 64 + col];
        v1 = vh[(size_t)(kr + 2 * t + 1) * 64 + col];
        v2 = vh[(size_t)(kr + 2 * t + 8) * 64 + col];
        v3 = vh[(size_t)(kr + 2 * t + 9) * 64 + col];
        vv.z = v0 | (v1 << 16);
        vv.w = v2 | (v3 << 16);
    }
    g_kf[idx] = kv;
    g_vf[idx] = vv;
}

// ---------------------------------------------------------------------------
// Attention stage 1 (fp16 m16n8k16): split-K partials.
// Softmax in log2 domain (log2e folded into q): P = ex2(S'), no FMUL.
// lsum via ones-B mma (tensor pipe) -> no FADD chain, no end shuffles.
// grid = (8 ci, 64 qb, 4 b)
// ---------------------------------------------------------------------------
#define ATT_SMEM_BYTES 32768

__global__ __launch_bounds__(256, 2) void attn_part_kernel()
{
    extern __shared__ uint4 sm4[];
    const uint32_t smb = (uint32_t)__cvta_generic_to_shared(sm4);

    const int ci = blockIdx.x;
    const int qb = blockIdx.y;
    const int b  = blockIdx.z;
    const int kstart = ci * KCHUNK;
    if (kstart > qb) return;
    const int kend = min(kstart + KCHUNK, qb + 1);

    const int tid = threadIdx.x;
    const int w = tid >> 5;
    const int l = tid & 31;
    const int g = l >> 2;
    const int t = l & 3;
    const int wr = w & 3;
    const int wg = w >> 2;

    uint32_t qa[4][4];
    {
        const uint32_t* qu = g_q + ((size_t)b * LSEQ + (size_t)qb * 64 + 16 * wr + g) * 32;
        const uint32_t* qu8 = qu + 8 * 32;
        #pragma unroll
        for (int kt = 0; kt < 4; kt++) {
            qa[kt][0] = qu[kt * 8 + t];
            qa[kt][1] = qu8[kt * 8 + t];
            qa[kt][2] = qu[kt * 8 + t + 4];
            qa[kt][3] = qu8[kt * 8 + t + 4];
        }
    }

    float o[8][4];
    #pragma unroll
    for (int nt = 0; nt < 8; nt++)
        #pragma unroll
        for (int j = 0; j < 4; j++) o[nt][j] = 0.f;
    float lfrag[4] = {0.f, 0.f, 0.f, 0.f};   // row-sum accumulator (ones-mma)
    const uint32_t ONES = 0x3C003C00u;       // half2(1.0, 1.0)

    auto stage = [&](int kb, int p) {
        const uint4* kp = g_kf + (size_t)(b * NQB + kb) * 512;
        const uint4* vp = g_vf + (size_t)(b * NQB + kb) * 512;
        uint32_t kd = smb + (uint32_t)p * 8192;
        uint32_t vd = smb + 16384u + (uint32_t)p * 8192;
        #pragma unroll
        for (int i = 0; i < 2; i++) {
            int u = tid + i * 256;
            cp16(kd + (uint32_t)u * 16, kp + u);
            cp16(vd + (uint32_t)u * 16, vp + u);
        }
        CP_COMMIT();
    };

    stage(kstart, 0);

    for (int kb = kstart; kb < kend; kb++) {
        const int p = (kb - kstart) & 1;
        CP_WAIT0();
        __syncthreads();
        const uint4* Kc = sm4 + p * 512;
        const uint4* Vc = sm4 + 1024 + p * 512;

        if (kb + 1 < kend) stage(kb + 1, 1 - p);

        // ---- S' = Q @ K^T (scale & log2e folded into Q) ----
        float s[4][4];
        #pragma unroll
        for (int ntl = 0; ntl < 4; ntl++)
            #pragma unroll
            for (int j = 0; j < 4; j++) s[ntl][j] = 0.f;

        #pragma unroll
        for (int kt = 0; kt < 4; kt++) {
            #pragma unroll
            for (int pp = 0; pp < 2; pp++) {
                uint4 f = Kc[(kt * 4 + wg * 2 + pp) * 32 + l];
                mma_f16(s[2 * pp],     qa[kt][0], qa[kt][1], qa[kt][2], qa[kt][3], f.x, f.y);
                mma_f16(s[2 * pp + 1], qa[kt][0], qa[kt][1], qa[kt][2], qa[kt][3], f.z, f.w);
            }
        }

        // causal mask on diagonal tile
        if (kb == qb) {
            int r0 = 16 * wr + g;
            #pragma unroll
            for (int ntl = 0; ntl < 4; ntl++) {
                int c = (wg * 4 + ntl) * 8 + 2 * t;
                if (c     > r0)     s[ntl][0] = -1e30f;
                if (c + 1 > r0)     s[ntl][1] = -1e30f;
                if (c     > r0 + 8) s[ntl][2] = -1e30f;
                if (c + 1 > r0 + 8) s[ntl][3] = -1e30f;
            }
        }

        // ---- P = 2^(S') (bare MUFU; masked -> 0) ----
        #pragma unroll
        for (int ntl = 0; ntl < 4; ntl++) {
            s[ntl][0] = ex2f(s[ntl][0]);
            s[ntl][1] = ex2f(s[ntl][1]);
            s[ntl][2] = ex2f(s[ntl][2]);
            s[ntl][3] = ex2f(s[ntl][3]);
        }

        // ---- O += P @ V ; lsum += P @ ones (tensor pipe) ----
        #pragma unroll
        for (int kk = 0; kk < 2; kk++) {
            uint32_t a0 = packh2(s[2 * kk][0],     s[2 * kk][1]);
            uint32_t a1 = packh2(s[2 * kk][2],     s[2 * kk][3]);
            uint32_t a2 = packh2(s[2 * kk + 1][0], s[2 * kk + 1][1]);
            uint32_t a3 = packh2(s[2 * kk + 1][2], s[2 * kk + 1][3]);
            mma_f16(lfrag, a0, a1, a2, a3, ONES, ONES);
            int kc = wg * 2 + kk;
            #pragma unroll
            for (int ntp = 0; ntp < 4; ntp++) {
                uint4 f = Vc[(kc * 4 + ntp) * 32 + l];
                mma_f16(o[2 * ntp],     a0, a1, a2, a3, f.x, f.y);
                mma_f16(o[2 * ntp + 1], a0, a1, a2, a3, f.z, f.w);
            }
        }
    }

    // lfrag[0] = row (16wr+g) sum over this warp's 32 keys (identical in all
    // t lanes); lfrag[2] = row +8. No shuffle reduction needed.
    const float lsum0 = lfrag[0];
    const float lsum1 = lfrag[2];

    float* smemO = (float*)sm4;
    float* lvec  = (float*)sm4 + 64 * 68;

    __syncthreads();
    if (wg == 0) {
        #pragma unroll
        for (int nt = 0; nt < 8; nt++) {
            int c = nt * 8 + 2 * t;
            smemO[(16 * wr + g) * 68 + c]         = o[nt][0];
            smemO[(16 * wr + g) * 68 + c + 1]     = o[nt][1];
            smemO[(16 * wr + g + 8) * 68 + c]     = o[nt][2];
            smemO[(16 * wr + g + 8) * 68 + c + 1] = o[nt][3];
        }
        if (t == 0) { lvec[16 * wr + g] = lsum0; lvec[16 * wr + g + 8] = lsum1; }
    }
    __syncthreads();
    if (wg == 1) {
        #pragma unroll
        for (int nt = 0; nt < 8; nt++) {
            int c = nt * 8 + 2 * t;
            smemO[(16 * wr + g) * 68 + c]         += o[nt][0];
            smemO[(16 * wr + g) * 68 + c + 1]     += o[nt][1];
            smemO[(16 * wr + g + 8) * 68 + c]     += o[nt][2];
            smemO[(16 * wr + g + 8) * 68 + c + 1] += o[nt][3];
        }
        if (t == 0) { lvec[16 * wr + g] += lsum0; lvec[16 * wr + g + 8] += lsum1; }
    }
    __syncthreads();

    const int item = (b * NQB + qb) * MAXCH + ci;
    {
        int row = tid >> 2;
        int c0 = (tid & 3) * 16;
        float* dst = g_opart + (size_t)item * 4096;
        #pragma unroll
        for (int j = 0; j < 4; j++)
            *(float4*)&dst[row * 64 + c0 + j * 4] = *(float4*)&smemO[row * 68 + c0 + j * 4];
        if ((tid & 3) == 0) g_lpart[item * 64 + row] = lvec[row];
    }
}

// ---------------------------------------------------------------------------
// Attention stage 2: elementwise reduce. (unchanged)
// ---------------------------------------------------------------------------
__global__ __launch_bounds__(256) void attn_reduce_kernel(float* __restrict__ out)
{
    int id = blockIdx.x * 256 + threadIdx.x;   // 262144
    int c4  = id & 15;
    int row = (id >> 4) & 63;
    int qb  = (id >> 10) & 63;
    int b   = id >> 16;
    int nch = qb / KCHUNK + 1;
    int base_item = (b * NQB + qb) * MAXCH;

    float4 acc = make_float4(0.f, 0.f, 0.f, 0.f);
    float lac = 0.f;
    for (int ci = 0; ci < nch; ci++) {
        const float4 v = *(const float4*)&g_opart[(size_t)(base_item + ci) * 4096 + row * 64 + c4 * 4];
        acc.x += v.x; acc.y += v.y; acc.z += v.z; acc.w += v.w;
        lac += g_lpart[(base_item + ci) * 64 + row];
    }
    float inv = 1.0f / lac;
    acc.x *= inv; acc.y *= inv; acc.z *= inv; acc.w *= inv;
    size_t orow = ((size_t)b * LSEQ + (size_t)qb * 64 + row) * DKH;
    *(float4*)&out[orow + c4 * 4] = acc;
}

// ---------------------------------------------------------------------------
extern "C" void kernel_launch(void* const* d_in, const int* in_sizes, int n_in,
                              void* d_out, int out_size)
{
    const float* Q  = (const float*)d_in[0];
    const float* K  = (const float*)d_in[1];
    const float* V  = (const float*)d_in[2];
    const float* Wq = (const float*)d_in[3];
    const float* bq = (const float*)d_in[4];
    const float* Wk = (const float*)d_in[5];
    const float* bk = (const float*)d_in[6];
    const float* Wv = (const float*)d_in[7];
    const float* bv = (const float*)d_in[8];
    float* out = (float*)d_out;

    cudaFuncSetAttribute(proj3_kernel, cudaFuncAttributeMaxDynamicSharedMemorySize,
                         P3_SMEM_BYTES);
    cudaFuncSetAttribute(attn_part_kernel, cudaFuncAttributeMaxDynamicSharedMemorySize,
                         ATT_SMEM_BYTES);

    wfrag16_kernel<<<96, 256>>>(Wq, Wk, Wv);

    dim3 pg(MROWS / 128, 1, 3);
    proj3_kernel<<<pg, 256, P3_SMEM_BYTES>>>(Q, K, V, bq, bk, bv);

    repack_kernel<<<512, 256>>>();

    dim3 ag(MAXCH, NQB, BATCH);
    attn_part_kernel<<<ag, 256, ATT_SMEM_BYTES>>>();

    attn_reduce_kernel<<<1024, 256>>>(out);
}